// round 16
// baseline (speedup 1.0000x reference)
#include <cuda_runtime.h>
#include <cstdint>

#define EDGES 800000
#define NODES 50000
#define DD 128
#define TILE 64
#define NT 256
#define NT2 128
#define WPAD 132
#define IPAD2 132
#define IPADN 260

using u64 = unsigned long long;

__device__ float g_bufA[(size_t)EDGES * DD];
__device__ float g_bufB[(size_t)EDGES * DD];
__device__ float g_preA[NODES * DD];
__device__ float g_preB[NODES * DD];
__device__ float g_agg[NODES * DD];
__device__ float g_cnt[NODES];
__device__ float g_csum[NODES * 3];
__device__ float g_npre[NODES * DD];
__device__ float g_bnsum[8 * 128];
__device__ float g_scale[4 * 128];
__device__ float g_shift[4 * 128];

#define FMA2(d, a, b, c) asm("fma.rn.f32x2 %0, %1, %2, %3;" : "=l"(d) : "l"(a), "l"(b), "l"(c))
#define PACK2(d, lo, hi) asm("mov.b64 %0, {%1, %2};" : "=l"(d) : "f"(lo), "f"(hi))
#define UNPACK2(lo, hi, s) asm("mov.b64 {%0, %1}, %2;" : "=f"(lo), "=f"(hi) : "l"(s))

__device__ __forceinline__ void unpack_row(const u64 a[4], float v[8]) {
    UNPACK2(v[0], v[1], a[0]);
    UNPACK2(v[2], v[3], a[1]);
    UNPACK2(v[4], v[5], a[2]);
    UNPACK2(v[6], v[7], a[3]);
}

// 64-row tile core (k_pre / k_node1 / k_node2): 256 thr, 4 rows x (4+4) cols per thread.
template <int KIN, int IPAD>
__device__ __forceinline__ void gemm_core(const float* __restrict__ Ws,
                                          const float* __restrict__ in_t,
                                          u64 acc[4][4], int tx, int ty) {
    const float* ip = in_t + (ty * 4) * IPAD;
    const float* wp1 = Ws + tx * 4;
    const float* wp2 = Ws + 64 + tx * 4;
#pragma unroll
    for (int i = 0; i < 4; i++)
#pragma unroll
        for (int j = 0; j < 4; j++) acc[i][j] = 0ull;
#pragma unroll 2
    for (int kk = 0; kk < KIN; kk += 4) {
        float a[4][4];
        *reinterpret_cast<float4*>(a[0]) = *reinterpret_cast<const float4*>(ip + kk);
        *reinterpret_cast<float4*>(a[1]) = *reinterpret_cast<const float4*>(ip + IPAD + kk);
        *reinterpret_cast<float4*>(a[2]) = *reinterpret_cast<const float4*>(ip + 2 * IPAD + kk);
        *reinterpret_cast<float4*>(a[3]) = *reinterpret_cast<const float4*>(ip + 3 * IPAD + kk);
#pragma unroll
        for (int u = 0; u < 4; u++) {
            size_t ko = (size_t)(kk + u) * WPAD;
            ulonglong2 wA = *reinterpret_cast<const ulonglong2*>(wp1 + ko);
            ulonglong2 wB = *reinterpret_cast<const ulonglong2*>(wp2 + ko);
            u64 w0 = wA.x, w1 = wA.y, w2 = wB.x, w3 = wB.y;
            u64 ap[4];
            PACK2(ap[0], a[0][u], a[0][u]);
            PACK2(ap[1], a[1][u], a[1][u]);
            PACK2(ap[2], a[2][u], a[2][u]);
            PACK2(ap[3], a[3][u], a[3][u]);
#pragma unroll
            for (int i = 0; i < 4; i++) {
                FMA2(acc[i][0], ap[i], w0, acc[i][0]);
                FMA2(acc[i][1], ap[i], w1, acc[i][1]);
                FMA2(acc[i][2], ap[i], w2, acc[i][2]);
                FMA2(acc[i][3], ap[i], w3, acc[i][3]);
            }
        }
    }
}

// 8-rows-per-thread core (edge GEMMs, 128 threads, ty in 0..7): 8 rows x (4+4) cols.
__device__ __forceinline__ void gemm_core8(const float* __restrict__ Ws,
                                           const float* __restrict__ in_t,
                                           u64 acc[8][4], int tx, int ty) {
    const float* ip = in_t + (ty * 8) * IPAD2;
    const float* wp1 = Ws + tx * 4;
    const float* wp2 = Ws + 64 + tx * 4;
#pragma unroll
    for (int i = 0; i < 8; i++)
#pragma unroll
        for (int j = 0; j < 4; j++) acc[i][j] = 0ull;
    for (int kk = 0; kk < DD; kk += 4) {
        float a[8][4];
#pragma unroll
        for (int r = 0; r < 8; r++)
            *reinterpret_cast<float4*>(a[r]) =
                *reinterpret_cast<const float4*>(ip + r * IPAD2 + kk);
#pragma unroll
        for (int u = 0; u < 4; u++) {
            size_t ko = (size_t)(kk + u) * WPAD;
            ulonglong2 wA = *reinterpret_cast<const ulonglong2*>(wp1 + ko);
            ulonglong2 wB = *reinterpret_cast<const ulonglong2*>(wp2 + ko);
            u64 w0 = wA.x, w1 = wA.y, w2 = wB.x, w3 = wB.y;
#pragma unroll
            for (int i = 0; i < 8; i++) {
                u64 ap;
                PACK2(ap, a[i][u], a[i][u]);
                FMA2(acc[i][0], ap, w0, acc[i][0]);
                FMA2(acc[i][1], ap, w1, acc[i][1]);
                FMA2(acc[i][2], ap, w2, acc[i][2]);
                FMA2(acc[i][3], ap, w3, acc[i][3]);
            }
        }
    }
}

// BN stats for 256-thread kernels (16 row-groups). Called ONCE per CTA at kernel end.
__device__ __forceinline__ void tile_stats(float* st, const float bs[8], const float bq[8],
                                           int ob1, int ob2, int ty, int tid, int li) {
    __syncthreads();
#pragma unroll
    for (int j = 0; j < 4; j++) {
        st[ty * 128 + ob1 + j] = bs[j];
        st[ty * 128 + ob2 + j] = bs[4 + j];
        st[2048 + ty * 128 + ob1 + j] = bq[j];
        st[2048 + ty * 128 + ob2 + j] = bq[4 + j];
    }
    __syncthreads();
    if (tid < 128) {
        float s = 0.f, q = 0.f;
#pragma unroll
        for (int gi = 0; gi < 16; gi++) {
            s += st[gi * 128 + tid];
            q += st[2048 + gi * 128 + tid];
        }
        atomicAdd(&g_bnsum[(2 * li) * 128 + tid], s);
        atomicAdd(&g_bnsum[(2 * li + 1) * 128 + tid], q);
    }
}

// BN stats for 128-thread kernels (8 row-groups). Called ONCE per CTA at kernel end.
__device__ __forceinline__ void tile_stats8(float* st, const float bs[8], const float bq[8],
                                            int ob1, int ob2, int ty, int tid, int li) {
    __syncthreads();
#pragma unroll
    for (int j = 0; j < 4; j++) {
        st[ty * 128 + ob1 + j] = bs[j];
        st[ty * 128 + ob2 + j] = bs[4 + j];
        st[1024 + ty * 128 + ob1 + j] = bq[j];
        st[1024 + ty * 128 + ob2 + j] = bq[4 + j];
    }
    __syncthreads();
    {
        float s = 0.f, q = 0.f;
#pragma unroll
        for (int gi = 0; gi < 8; gi++) {
            s += st[gi * 128 + tid];
            q += st[1024 + gi * 128 + tid];
        }
        atomicAdd(&g_bnsum[(2 * li) * 128 + tid], s);
        atomicAdd(&g_bnsum[(2 * li + 1) * 128 + tid], q);
    }
}

__global__ void k_zero() {
    int i = blockIdx.x * blockDim.x + threadIdx.x;
    int st = gridDim.x * blockDim.x;
    for (int j = i; j < NODES * DD; j += st) g_agg[j] = 0.f;
    for (int j = i; j < NODES; j += st) g_cnt[j] = 0.f;
    for (int j = i; j < NODES * 3; j += st) g_csum[j] = 0.f;
    for (int j = i; j < 8 * 128; j += st) g_bnsum[j] = 0.f;
}

// Node-sized GEMM: out[n] = h[n] @ W1[:, woff:woff+128]^T. WHICH selects the
// __device__ output buffer in device code (host-side symbol = shadow address).
template <int WHICH>
__global__ void __launch_bounds__(NT, 2) k_pre(const float* __restrict__ h,
                                               const float* __restrict__ W, int wstride,
                                               int woff) {
    float* out = (WHICH == 0) ? g_preA : g_preB;
    extern __shared__ float sm[];
    float* Ws = sm;
    float* in_t = Ws + DD * WPAD;
    int tid = threadIdx.x;
    for (int idx = tid; idx < DD * DD; idx += NT) {
        int o = idx >> 7, k = idx & 127;
        Ws[k * WPAD + o] = W[o * wstride + woff + k];
    }
    int wi = tid >> 5, l = tid & 31;
    int tx = tid & 15, ty = tid >> 4;
    int ob1 = tx * 4, ob2 = 64 + tx * 4;
    __syncthreads();
    int ntiles = (NODES + TILE - 1) / TILE;
    for (int tile = blockIdx.x; tile < ntiles; tile += gridDim.x) {
        int n0 = tile * TILE;
        for (int el = wi; el < TILE; el += 8) {
            int n = n0 + el;
            float4 v = make_float4(0.f, 0.f, 0.f, 0.f);
            if (n < NODES) v = reinterpret_cast<const float4*>(h)[n * 32 + l];
            *reinterpret_cast<float4*>(&in_t[el * IPAD2 + 4 * l]) = v;
        }
        __syncthreads();
        u64 acc[4][4];
        gemm_core<DD, IPAD2>(Ws, in_t, acc, tx, ty);
#pragma unroll
        for (int i = 0; i < 4; i++) {
            int n = n0 + ty * 4 + i;
            if (n < NODES) {
                float v[8];
                unpack_row(acc[i], v);
                *reinterpret_cast<float4*>(&out[n * DD + ob1]) =
                    make_float4(v[0], v[1], v[2], v[3]);
                *reinterpret_cast<float4*>(&out[n * DD + ob2]) =
                    make_float4(v[4], v[5], v[6], v[7]);
            }
        }
        __syncthreads();
    }
}

// Edge layer 1 as gather-add: x1[e] = preA[row] + preB[col] + radial*wr + b, fused BN stats.
__global__ void __launch_bounds__(256) k_e1gather(const float* __restrict__ coord,
                                                  const int* __restrict__ rowp,
                                                  const int* __restrict__ colp,
                                                  const float* __restrict__ w1,
                                                  const float* __restrict__ b1) {
    __shared__ float sred[2048];
    int tid = threadIdx.x;
    int l = tid & 31, wi = tid >> 5;
    float wr0 = w1[(4 * l + 0) * 257 + 256];
    float wr1 = w1[(4 * l + 1) * 257 + 256];
    float wr2 = w1[(4 * l + 2) * 257 + 256];
    float wr3 = w1[(4 * l + 3) * 257 + 256];
    float4 b4 = reinterpret_cast<const float4*>(b1)[l];
    float bs0 = 0.f, bs1 = 0.f, bs2 = 0.f, bs3 = 0.f;
    float bq0 = 0.f, bq1 = 0.f, bq2 = 0.f, bq3 = 0.f;
    int gw = (blockIdx.x * blockDim.x + tid) >> 5;
    int nw = (gridDim.x * blockDim.x) >> 5;
    for (int e = gw; e < EDGES; e += nw) {
        int r = rowp[e], c = colp[e];
        float d = (l < 3) ? (coord[r * 3 + l] - coord[c * 3 + l]) : 0.f;
        float p = d * d;
        p += __shfl_xor_sync(0xffffffffu, p, 1);
        p += __shfl_xor_sync(0xffffffffu, p, 2);
        p = __shfl_sync(0xffffffffu, p, 0);
        float4 a = reinterpret_cast<const float4*>(g_preA)[r * 32 + l];
        float4 bb = reinterpret_cast<const float4*>(g_preB)[c * 32 + l];
        float v0 = a.x + bb.x + p * wr0 + b4.x;
        float v1 = a.y + bb.y + p * wr1 + b4.y;
        float v2 = a.z + bb.z + p * wr2 + b4.z;
        float v3 = a.w + bb.w + p * wr3 + b4.w;
        reinterpret_cast<float4*>(g_bufA)[(size_t)e * 32 + l] = make_float4(v0, v1, v2, v3);
        bs0 += v0; bs1 += v1; bs2 += v2; bs3 += v3;
        bq0 += v0 * v0; bq1 += v1 * v1; bq2 += v2 * v2; bq3 += v3 * v3;
        if (l == 0) atomicAdd(&g_cnt[r], 1.0f);
    }
    sred[wi * 128 + 4 * l + 0] = bs0;
    sred[wi * 128 + 4 * l + 1] = bs1;
    sred[wi * 128 + 4 * l + 2] = bs2;
    sred[wi * 128 + 4 * l + 3] = bs3;
    sred[1024 + wi * 128 + 4 * l + 0] = bq0;
    sred[1024 + wi * 128 + 4 * l + 1] = bq1;
    sred[1024 + wi * 128 + 4 * l + 2] = bq2;
    sred[1024 + wi * 128 + 4 * l + 3] = bq3;
    __syncthreads();
    if (tid < 128) {
        float s = 0.f, q = 0.f;
#pragma unroll
        for (int gi = 0; gi < 8; gi++) {
            s += sred[gi * 128 + tid];
            q += sred[1024 + gi * 128 + tid];
        }
        atomicAdd(&g_bnsum[tid], s);
        atomicAdd(&g_bnsum[128 + tid], q);
    }
}

__global__ void k_bn_fin(int li, const float* __restrict__ g, const float* __restrict__ be,
                         float cnt) {
    int o = threadIdx.x;
    float s = g_bnsum[(2 * li) * 128 + o];
    float q = g_bnsum[(2 * li + 1) * 128 + o];
    float m = s / cnt;
    float var = q / cnt - m * m;
    float sc = rsqrtf(var + 1e-5f) * g[o];
    g_scale[li * 128 + o] = sc;
    g_shift[li * 128 + o] = be[o] - m * sc;
}

// Edge GEMM: 64-row tile, 128 threads, 8 rows x (4+4) cols per thread, 2 CTAs/SM.
// BN stats accumulate in REGISTERS across all tiles; one smem reduce at kernel end.
template <bool DO_AGG>
__global__ void __launch_bounds__(NT2, 2) k_edge_mid(const float* __restrict__ W,
                                                     const float* __restrict__ bvec,
                                                     const int* __restrict__ rowp) {
    extern __shared__ float sm[];
    float* Ws = sm;
    float* in_t = Ws + DD * WPAD;
    int* rowi = reinterpret_cast<int*>(in_t + TILE * IPAD2);
    const float* src = DO_AGG ? g_bufB : g_bufA;
    float* dst = DO_AGG ? g_bufA : g_bufB;
    const int li_in = DO_AGG ? 1 : 0;
    const int li_out = DO_AGG ? 2 : 1;
    int tid = threadIdx.x;
    for (int idx = tid; idx < DD * DD; idx += NT2) {
        int o = idx >> 7, k = idx & 127;
        Ws[k * WPAD + o] = W[idx];
    }
    int wi = tid >> 5, l = tid & 31;
    int tx = tid & 15, ty = tid >> 4;  // ty in 0..7
    int ob1 = tx * 4, ob2 = 64 + tx * 4;
    float4 sc4 = reinterpret_cast<const float4*>(g_scale + li_in * 128)[l];
    float4 sh4 = reinterpret_cast<const float4*>(g_shift + li_in * 128)[l];
    float bias[8];
#pragma unroll
    for (int j = 0; j < 4; j++) {
        bias[j] = bvec[ob1 + j];
        bias[4 + j] = bvec[ob2 + j];
    }
    float bs[8], bq[8];
#pragma unroll
    for (int j = 0; j < 8; j++) { bs[j] = 0.f; bq[j] = 0.f; }
    __syncthreads();
    for (int tile = blockIdx.x; tile < EDGES / TILE; tile += gridDim.x) {
        int e0 = tile * TILE;
        for (int el = wi; el < TILE; el += 4) {
            int e = e0 + el;
            float4 v = reinterpret_cast<const float4*>(src)[(size_t)e * 32 + l];
            v.x = fmaxf(fmaf(v.x, sc4.x, sh4.x), 0.f);
            v.y = fmaxf(fmaf(v.y, sc4.y, sh4.y), 0.f);
            v.z = fmaxf(fmaf(v.z, sc4.z, sh4.z), 0.f);
            v.w = fmaxf(fmaf(v.w, sc4.w, sh4.w), 0.f);
            *reinterpret_cast<float4*>(&in_t[el * IPAD2 + 4 * l]) = v;
            if (DO_AGG && l == 0) rowi[el] = rowp[e];
        }
        __syncthreads();
        if (DO_AGG) {
            for (int t2 = tid; t2 < TILE * 32; t2 += NT2) {
                int el = t2 >> 5, ch = t2 & 31;
                float4 v = *reinterpret_cast<const float4*>(&in_t[el * IPAD2 + ch * 4]);
                float* dp = &g_agg[rowi[el] * DD + ch * 4];
                asm volatile("red.global.add.v4.f32 [%0], {%1,%2,%3,%4};" ::"l"(dp), "f"(v.x),
                             "f"(v.y), "f"(v.z), "f"(v.w)
                             : "memory");
            }
        }
        u64 acc[8][4];
        gemm_core8(Ws, in_t, acc, tx, ty);
#pragma unroll
        for (int i = 0; i < 8; i++) {
            int e = e0 + ty * 8 + i;
            float v[8];
            unpack_row(acc[i], v);
#pragma unroll
            for (int j = 0; j < 8; j++) {
                v[j] += bias[j];
                bs[j] += v[j];
                bq[j] += v[j] * v[j];
            }
            *reinterpret_cast<float4*>(&dst[(size_t)e * DD + ob1]) =
                make_float4(v[0], v[1], v[2], v[3]);
            *reinterpret_cast<float4*>(&dst[(size_t)e * DD + ob2]) =
                make_float4(v[4], v[5], v[6], v[7]);
        }
        __syncthreads();
    }
    tile_stats8(in_t, bs, bq, ob1, ob2, ty, tid, li_out);
}

__global__ void k_coord(const float* __restrict__ coord, const int* __restrict__ rowp,
                        const int* __restrict__ colp, const float* __restrict__ cw2) {
    int l = threadIdx.x & 31;
    int gw = (blockIdx.x * blockDim.x + threadIdx.x) >> 5;
    int nw = (gridDim.x * blockDim.x) >> 5;
    float4 sc = reinterpret_cast<const float4*>(g_scale + 2 * 128)[l];
    float4 sh = reinterpret_cast<const float4*>(g_shift + 2 * 128)[l];
    float4 w4 = reinterpret_cast<const float4*>(cw2)[l];
    for (int e = gw; e < EDGES; e += nw) {
        float4 y = reinterpret_cast<const float4*>(g_bufA)[(size_t)e * 32 + l];
        y.x = fmaxf(fmaf(y.x, sc.x, sh.x), 0.f);
        y.y = fmaxf(fmaf(y.y, sc.y, sh.y), 0.f);
        y.z = fmaxf(fmaf(y.z, sc.z, sh.z), 0.f);
        y.w = fmaxf(fmaf(y.w, sc.w, sh.w), 0.f);
        float p = y.x * w4.x + y.y * w4.y + y.z * w4.z + y.w * w4.w;
#pragma unroll
        for (int off = 16; off > 0; off >>= 1) p += __shfl_xor_sync(0xffffffffu, p, off);
        if (l < 3) {
            int r = rowp[e], c = colp[e];
            float d = coord[r * 3 + l] - coord[c * 3 + l];
            float t = fminf(fmaxf(d * p, -100.f), 100.f);
            atomicAdd(&g_csum[r * 3 + l], t);
        }
    }
}

__global__ void __launch_bounds__(NT) k_node1(const float* __restrict__ h,
                                              const float* __restrict__ W,
                                              const float* __restrict__ bvec) {
    extern __shared__ float sm[];
    float* Ws = sm;
    float* in_t = Ws + 256 * WPAD;
    int tid = threadIdx.x;
    for (int idx = tid; idx < DD * 256; idx += NT) {
        int o = idx >> 8, k = idx & 255;
        Ws[k * WPAD + o] = W[idx];
    }
    int wi = tid >> 5, l = tid & 31;
    int tx = tid & 15, ty = tid >> 4;
    int ob1 = tx * 4, ob2 = 64 + tx * 4;
    float bias[8];
#pragma unroll
    for (int j = 0; j < 4; j++) {
        bias[j] = bvec[ob1 + j];
        bias[4 + j] = bvec[ob2 + j];
    }
    float bs[8], bq[8];
#pragma unroll
    for (int j = 0; j < 8; j++) { bs[j] = 0.f; bq[j] = 0.f; }
    __syncthreads();
    int ntiles = (NODES + TILE - 1) / TILE;
    for (int tile = blockIdx.x; tile < ntiles; tile += gridDim.x) {
        int n0 = tile * TILE;
        for (int el = wi; el < TILE; el += 8) {
            int n = n0 + el;
            if (n < NODES) {
                float4 hv = reinterpret_cast<const float4*>(h)[n * 32 + l];
                *reinterpret_cast<float4*>(&in_t[el * IPADN + 4 * l]) = hv;
                float invc = 1.f / fmaxf(g_cnt[n], 1.f);
                float4 av = reinterpret_cast<const float4*>(g_agg)[n * 32 + l];
                av.x *= invc; av.y *= invc; av.z *= invc; av.w *= invc;
                *reinterpret_cast<float4*>(&in_t[el * IPADN + DD + 4 * l]) = av;
            } else {
                float4 z = make_float4(0.f, 0.f, 0.f, 0.f);
                *reinterpret_cast<float4*>(&in_t[el * IPADN + 4 * l]) = z;
                *reinterpret_cast<float4*>(&in_t[el * IPADN + DD + 4 * l]) = z;
            }
        }
        __syncthreads();
        u64 acc[4][4];
        gemm_core<256, IPADN>(Ws, in_t, acc, tx, ty);
#pragma unroll
        for (int i = 0; i < 4; i++) {
            int n = n0 + ty * 4 + i;
            float v[8];
            unpack_row(acc[i], v);
#pragma unroll
            for (int j = 0; j < 8; j++) v[j] += bias[j];
            if (n < NODES) {
#pragma unroll
                for (int j = 0; j < 8; j++) {
                    bs[j] += v[j];
                    bq[j] += v[j] * v[j];
                }
                *reinterpret_cast<float4*>(&g_npre[n * DD + ob1]) =
                    make_float4(v[0], v[1], v[2], v[3]);
                *reinterpret_cast<float4*>(&g_npre[n * DD + ob2]) =
                    make_float4(v[4], v[5], v[6], v[7]);
            }
        }
        __syncthreads();
    }
    tile_stats(in_t, bs, bq, ob1, ob2, ty, tid, 3);
}

__global__ void __launch_bounds__(NT, 2) k_node2(const float* __restrict__ h,
                                                 const float* __restrict__ W,
                                                 const float* __restrict__ bvec,
                                                 float* __restrict__ out) {
    extern __shared__ float sm[];
    float* Ws = sm;
    float* in_t = Ws + DD * WPAD;
    int tid = threadIdx.x;
    for (int idx = tid; idx < DD * DD; idx += NT) {
        int o = idx >> 7, k = idx & 127;
        Ws[k * WPAD + o] = W[idx];
    }
    int wi = tid >> 5, l = tid & 31;
    int tx = tid & 15, ty = tid >> 4;
    int ob1 = tx * 4, ob2 = 64 + tx * 4;
    float4 sc4 = reinterpret_cast<const float4*>(g_scale + 3 * 128)[l];
    float4 sh4 = reinterpret_cast<const float4*>(g_shift + 3 * 128)[l];
    float bias[8];
#pragma unroll
    for (int j = 0; j < 4; j++) {
        bias[j] = bvec[ob1 + j];
        bias[4 + j] = bvec[ob2 + j];
    }
    __syncthreads();
    int ntiles = (NODES + TILE - 1) / TILE;
    for (int tile = blockIdx.x; tile < ntiles; tile += gridDim.x) {
        int n0 = tile * TILE;
        for (int el = wi; el < TILE; el += 8) {
            int n = n0 + el;
            float4 v = make_float4(0.f, 0.f, 0.f, 0.f);
            if (n < NODES) {
                v = reinterpret_cast<const float4*>(g_npre)[n * 32 + l];
                v.x = fmaxf(fmaf(v.x, sc4.x, sh4.x), 0.f);
                v.y = fmaxf(fmaf(v.y, sc4.y, sh4.y), 0.f);
                v.z = fmaxf(fmaf(v.z, sc4.z, sh4.z), 0.f);
                v.w = fmaxf(fmaf(v.w, sc4.w, sh4.w), 0.f);
            }
            *reinterpret_cast<float4*>(&in_t[el * IPAD2 + 4 * l]) = v;
        }
        __syncthreads();
        u64 acc[4][4];
        gemm_core<DD, IPAD2>(Ws, in_t, acc, tx, ty);
#pragma unroll
        for (int i = 0; i < 4; i++) {
            int n = n0 + ty * 4 + i;
            if (n < NODES) {
                float v[8];
                unpack_row(acc[i], v);
#pragma unroll
                for (int j = 0; j < 4; j++) {
                    v[j] += bias[j] + h[n * DD + ob1 + j];
                    v[4 + j] += bias[4 + j] + h[n * DD + ob2 + j];
                }
                *reinterpret_cast<float4*>(&out[n * DD + ob1]) =
                    make_float4(v[0], v[1], v[2], v[3]);
                *reinterpret_cast<float4*>(&out[n * DD + ob2]) =
                    make_float4(v[4], v[5], v[6], v[7]);
            }
        }
        __syncthreads();
    }
}

__global__ void k_coord_fin(const float* __restrict__ coord, float* __restrict__ out) {
    int i = blockIdx.x * blockDim.x + threadIdx.x;
    if (i < NODES * 3)
        out[NODES * DD + i] = coord[i] + g_csum[i] / fmaxf(g_cnt[i / 3], 1.f);
}

extern "C" void kernel_launch(void* const* d_in, const int* in_sizes, int n_in,
                              void* d_out, int out_size) {
    const float* h = (const float*)d_in[0];
    const float* coord = (const float*)d_in[1];
    const int* ei = (const int*)d_in[2];
    const float* e_w1 = (const float*)d_in[3];
    const float* e_b1 = (const float*)d_in[4];
    const float* e_g1 = (const float*)d_in[5];
    const float* e_be1 = (const float*)d_in[6];
    const float* e_w2 = (const float*)d_in[7];
    const float* e_b2 = (const float*)d_in[8];
    const float* e_g2 = (const float*)d_in[9];
    const float* e_be2 = (const float*)d_in[10];
    const float* n_w1 = (const float*)d_in[11];
    const float* n_b1 = (const float*)d_in[12];
    const float* n_g1 = (const float*)d_in[13];
    const float* n_be1 = (const float*)d_in[14];
    const float* n_w2 = (const float*)d_in[15];
    const float* n_b2 = (const float*)d_in[16];
    const float* c_w1 = (const float*)d_in[17];
    const float* c_b1 = (const float*)d_in[18];
    const float* c_g1 = (const float*)d_in[19];
    const float* c_be1 = (const float*)d_in[20];
    const float* c_w2 = (const float*)d_in[21];
    const int* rowp = ei;
    const int* colp = ei + EDGES;
    float* out = (float*)d_out;

    int S2 = (DD * WPAD + TILE * IPAD2) * 4 + TILE * 4;
    int Sn1 = (256 * WPAD + TILE * IPADN) * 4;
    cudaFuncSetAttribute(k_pre<0>, cudaFuncAttributeMaxDynamicSharedMemorySize, S2);
    cudaFuncSetAttribute(k_pre<1>, cudaFuncAttributeMaxDynamicSharedMemorySize, S2);
    cudaFuncSetAttribute(k_edge_mid<false>, cudaFuncAttributeMaxDynamicSharedMemorySize, S2);
    cudaFuncSetAttribute(k_edge_mid<true>, cudaFuncAttributeMaxDynamicSharedMemorySize, S2);
    cudaFuncSetAttribute(k_node1, cudaFuncAttributeMaxDynamicSharedMemorySize, Sn1);
    cudaFuncSetAttribute(k_node2, cudaFuncAttributeMaxDynamicSharedMemorySize, S2);

    k_zero<<<256, 256>>>();
    k_pre<0><<<296, NT, S2>>>(h, e_w1, 257, 0);
    k_pre<1><<<296, NT, S2>>>(h, e_w1, 257, 128);
    k_e1gather<<<740, 256>>>(coord, rowp, colp, e_w1, e_b1);
    k_bn_fin<<<1, 128>>>(0, e_g1, e_be1, (float)EDGES);
    k_edge_mid<false><<<296, NT2, S2>>>(e_w2, e_b2, rowp);
    k_bn_fin<<<1, 128>>>(1, e_g2, e_be2, (float)EDGES);
    k_edge_mid<true><<<296, NT2, S2>>>(c_w1, c_b1, rowp);
    k_bn_fin<<<1, 128>>>(2, c_g1, c_be1, (float)EDGES);
    k_coord<<<740, 256>>>(coord, rowp, colp, c_w2);
    k_node1<<<148, NT, Sn1>>>(h, n_w1, n_b1);
    k_bn_fin<<<1, 128>>>(3, n_g1, n_be1, (float)NODES);
    k_node2<<<296, NT, S2>>>(h, n_w2, n_b2, out);
    k_coord_fin<<<(NODES * 3 + 255) / 256, 256>>>(coord, out);
}

// round 17
// speedup vs baseline: 1.0491x; 1.0491x over previous
#include <cuda_runtime.h>
#include <cstdint>

#define EDGES 800000
#define NODES 50000
#define DD 128
#define TILE 64
#define NT 256
#define NT2 128
#define WPAD 132
#define IPAD2 132
#define IPADN 260

using u64 = unsigned long long;

__device__ float g_bufA[(size_t)EDGES * DD];
__device__ float g_bufB[(size_t)EDGES * DD];
__device__ float g_preA[NODES * DD];
__device__ float g_preB[NODES * DD];
__device__ float g_agg[NODES * DD];
__device__ float g_cnt[NODES];
__device__ float g_csum[NODES * 3];
__device__ float g_npre[NODES * DD];
__device__ float g_bnsum[8 * 128];

#define FMA2(d, a, b, c) asm("fma.rn.f32x2 %0, %1, %2, %3;" : "=l"(d) : "l"(a), "l"(b), "l"(c))
#define PACK2(d, lo, hi) asm("mov.b64 %0, {%1, %2};" : "=l"(d) : "f"(lo), "f"(hi))
#define UNPACK2(lo, hi, s) asm("mov.b64 {%0, %1}, %2;" : "=f"(lo), "=f"(hi) : "l"(s))

__device__ __forceinline__ void unpack_row(const u64 a[4], float v[8]) {
    UNPACK2(v[0], v[1], a[0]);
    UNPACK2(v[2], v[3], a[1]);
    UNPACK2(v[4], v[5], a[2]);
    UNPACK2(v[6], v[7], a[3]);
}

// Inline BN affine for lane l (channels 4l..4l+3) of layer li; identical math to the
// old k_bn_fin (same op order -> identical numerics), computed redundantly per thread.
__device__ __forceinline__ void bn_affine(int li, float cnt, const float* __restrict__ g,
                                          const float* __restrict__ be, int l, float4& sc,
                                          float4& sh) {
    float4 s4 = reinterpret_cast<const float4*>(g_bnsum + 2 * li * 128)[l];
    float4 q4 = reinterpret_cast<const float4*>(g_bnsum + (2 * li + 1) * 128)[l];
    float4 gg = reinterpret_cast<const float4*>(g)[l];
    float4 bb = reinterpret_cast<const float4*>(be)[l];
    float m;
    m = s4.x / cnt; sc.x = rsqrtf(q4.x / cnt - m * m + 1e-5f) * gg.x; sh.x = bb.x - m * sc.x;
    m = s4.y / cnt; sc.y = rsqrtf(q4.y / cnt - m * m + 1e-5f) * gg.y; sh.y = bb.y - m * sc.y;
    m = s4.z / cnt; sc.z = rsqrtf(q4.z / cnt - m * m + 1e-5f) * gg.z; sh.z = bb.z - m * sc.z;
    m = s4.w / cnt; sc.w = rsqrtf(q4.w / cnt - m * m + 1e-5f) * gg.w; sh.w = bb.w - m * sc.w;
}

// 64-row tile core (k_pre / k_node1 / k_node2): 256 thr, 4 rows x (4+4) cols per thread.
template <int KIN, int IPAD>
__device__ __forceinline__ void gemm_core(const float* __restrict__ Ws,
                                          const float* __restrict__ in_t,
                                          u64 acc[4][4], int tx, int ty) {
    const float* ip = in_t + (ty * 4) * IPAD;
    const float* wp1 = Ws + tx * 4;
    const float* wp2 = Ws + 64 + tx * 4;
#pragma unroll
    for (int i = 0; i < 4; i++)
#pragma unroll
        for (int j = 0; j < 4; j++) acc[i][j] = 0ull;
#pragma unroll 2
    for (int kk = 0; kk < KIN; kk += 4) {
        float a[4][4];
        *reinterpret_cast<float4*>(a[0]) = *reinterpret_cast<const float4*>(ip + kk);
        *reinterpret_cast<float4*>(a[1]) = *reinterpret_cast<const float4*>(ip + IPAD + kk);
        *reinterpret_cast<float4*>(a[2]) = *reinterpret_cast<const float4*>(ip + 2 * IPAD + kk);
        *reinterpret_cast<float4*>(a[3]) = *reinterpret_cast<const float4*>(ip + 3 * IPAD + kk);
#pragma unroll
        for (int u = 0; u < 4; u++) {
            size_t ko = (size_t)(kk + u) * WPAD;
            ulonglong2 wA = *reinterpret_cast<const ulonglong2*>(wp1 + ko);
            ulonglong2 wB = *reinterpret_cast<const ulonglong2*>(wp2 + ko);
            u64 w0 = wA.x, w1 = wA.y, w2 = wB.x, w3 = wB.y;
            u64 ap[4];
            PACK2(ap[0], a[0][u], a[0][u]);
            PACK2(ap[1], a[1][u], a[1][u]);
            PACK2(ap[2], a[2][u], a[2][u]);
            PACK2(ap[3], a[3][u], a[3][u]);
#pragma unroll
            for (int i = 0; i < 4; i++) {
                FMA2(acc[i][0], ap[i], w0, acc[i][0]);
                FMA2(acc[i][1], ap[i], w1, acc[i][1]);
                FMA2(acc[i][2], ap[i], w2, acc[i][2]);
                FMA2(acc[i][3], ap[i], w3, acc[i][3]);
            }
        }
    }
}

// 8-rows-per-thread core (edge GEMMs, 128 threads, ty in 0..7): 8 rows x (4+4) cols.
__device__ __forceinline__ void gemm_core8(const float* __restrict__ Ws,
                                           const float* __restrict__ in_t,
                                           u64 acc[8][4], int tx, int ty) {
    const float* ip = in_t + (ty * 8) * IPAD2;
    const float* wp1 = Ws + tx * 4;
    const float* wp2 = Ws + 64 + tx * 4;
#pragma unroll
    for (int i = 0; i < 8; i++)
#pragma unroll
        for (int j = 0; j < 4; j++) acc[i][j] = 0ull;
    for (int kk = 0; kk < DD; kk += 4) {
        float a[8][4];
#pragma unroll
        for (int r = 0; r < 8; r++)
            *reinterpret_cast<float4*>(a[r]) =
                *reinterpret_cast<const float4*>(ip + r * IPAD2 + kk);
#pragma unroll
        for (int u = 0; u < 4; u++) {
            size_t ko = (size_t)(kk + u) * WPAD;
            ulonglong2 wA = *reinterpret_cast<const ulonglong2*>(wp1 + ko);
            ulonglong2 wB = *reinterpret_cast<const ulonglong2*>(wp2 + ko);
            u64 w0 = wA.x, w1 = wA.y, w2 = wB.x, w3 = wB.y;
#pragma unroll
            for (int i = 0; i < 8; i++) {
                u64 ap;
                PACK2(ap, a[i][u], a[i][u]);
                FMA2(acc[i][0], ap, w0, acc[i][0]);
                FMA2(acc[i][1], ap, w1, acc[i][1]);
                FMA2(acc[i][2], ap, w2, acc[i][2]);
                FMA2(acc[i][3], ap, w3, acc[i][3]);
            }
        }
    }
}

// BN stats for 256-thread kernels (16 row-groups), per tile.
__device__ __forceinline__ void tile_stats(float* st, const float bs[8], const float bq[8],
                                           int ob1, int ob2, int ty, int tid, int li) {
    __syncthreads();
#pragma unroll
    for (int j = 0; j < 4; j++) {
        st[ty * 128 + ob1 + j] = bs[j];
        st[ty * 128 + ob2 + j] = bs[4 + j];
        st[2048 + ty * 128 + ob1 + j] = bq[j];
        st[2048 + ty * 128 + ob2 + j] = bq[4 + j];
    }
    __syncthreads();
    if (tid < 128) {
        float s = 0.f, q = 0.f;
#pragma unroll
        for (int gi = 0; gi < 16; gi++) {
            s += st[gi * 128 + tid];
            q += st[2048 + gi * 128 + tid];
        }
        atomicAdd(&g_bnsum[(2 * li) * 128 + tid], s);
        atomicAdd(&g_bnsum[(2 * li + 1) * 128 + tid], q);
    }
    __syncthreads();
}

// BN stats for 128-thread kernels (8 row-groups), per tile.
__device__ __forceinline__ void tile_stats8(float* st, const float bs[8], const float bq[8],
                                            int ob1, int ob2, int ty, int tid, int li) {
    __syncthreads();
#pragma unroll
    for (int j = 0; j < 4; j++) {
        st[ty * 128 + ob1 + j] = bs[j];
        st[ty * 128 + ob2 + j] = bs[4 + j];
        st[1024 + ty * 128 + ob1 + j] = bq[j];
        st[1024 + ty * 128 + ob2 + j] = bq[4 + j];
    }
    __syncthreads();
    {
        float s = 0.f, q = 0.f;
#pragma unroll
        for (int gi = 0; gi < 8; gi++) {
            s += st[gi * 128 + tid];
            q += st[1024 + gi * 128 + tid];
        }
        atomicAdd(&g_bnsum[(2 * li) * 128 + tid], s);
        atomicAdd(&g_bnsum[(2 * li + 1) * 128 + tid], q);
    }
    __syncthreads();
}

__global__ void k_zero() {
    int i = blockIdx.x * blockDim.x + threadIdx.x;
    int st = gridDim.x * blockDim.x;
    float4 z = make_float4(0.f, 0.f, 0.f, 0.f);
    for (int j = i; j < NODES * DD / 4; j += st) reinterpret_cast<float4*>(g_agg)[j] = z;
    for (int j = i; j < NODES / 4; j += st) reinterpret_cast<float4*>(g_cnt)[j] = z;
    for (int j = i; j < NODES * 3 / 4; j += st) reinterpret_cast<float4*>(g_csum)[j] = z;
    for (int j = i; j < 8 * 128 / 4; j += st) reinterpret_cast<float4*>(g_bnsum)[j] = z;
}

// Node-sized GEMM: out[n] = h[n] @ W1[:, woff:woff+128]^T. WHICH selects the
// __device__ output buffer in device code (host-side symbol = shadow address).
template <int WHICH>
__global__ void __launch_bounds__(NT, 2) k_pre(const float* __restrict__ h,
                                               const float* __restrict__ W, int wstride,
                                               int woff) {
    float* out = (WHICH == 0) ? g_preA : g_preB;
    extern __shared__ float sm[];
    float* Ws = sm;
    float* in_t = Ws + DD * WPAD;
    int tid = threadIdx.x;
    for (int idx = tid; idx < DD * DD; idx += NT) {
        int o = idx >> 7, k = idx & 127;
        Ws[k * WPAD + o] = W[o * wstride + woff + k];
    }
    int wi = tid >> 5, l = tid & 31;
    int tx = tid & 15, ty = tid >> 4;
    int ob1 = tx * 4, ob2 = 64 + tx * 4;
    __syncthreads();
    int ntiles = (NODES + TILE - 1) / TILE;
    for (int tile = blockIdx.x; tile < ntiles; tile += gridDim.x) {
        int n0 = tile * TILE;
        for (int el = wi; el < TILE; el += 8) {
            int n = n0 + el;
            float4 v = make_float4(0.f, 0.f, 0.f, 0.f);
            if (n < NODES) v = reinterpret_cast<const float4*>(h)[n * 32 + l];
            *reinterpret_cast<float4*>(&in_t[el * IPAD2 + 4 * l]) = v;
        }
        __syncthreads();
        u64 acc[4][4];
        gemm_core<DD, IPAD2>(Ws, in_t, acc, tx, ty);
#pragma unroll
        for (int i = 0; i < 4; i++) {
            int n = n0 + ty * 4 + i;
            if (n < NODES) {
                float v[8];
                unpack_row(acc[i], v);
                *reinterpret_cast<float4*>(&out[n * DD + ob1]) =
                    make_float4(v[0], v[1], v[2], v[3]);
                *reinterpret_cast<float4*>(&out[n * DD + ob2]) =
                    make_float4(v[4], v[5], v[6], v[7]);
            }
        }
        __syncthreads();
    }
}

// Edge layer 1 as gather-add: x1[e] = preA[row] + preB[col] + radial*wr + b, fused BN stats.
__global__ void __launch_bounds__(256) k_e1gather(const float* __restrict__ coord,
                                                  const int* __restrict__ rowp,
                                                  const int* __restrict__ colp,
                                                  const float* __restrict__ w1,
                                                  const float* __restrict__ b1) {
    __shared__ float sred[2048];
    int tid = threadIdx.x;
    int l = tid & 31, wi = tid >> 5;
    float wr0 = w1[(4 * l + 0) * 257 + 256];
    float wr1 = w1[(4 * l + 1) * 257 + 256];
    float wr2 = w1[(4 * l + 2) * 257 + 256];
    float wr3 = w1[(4 * l + 3) * 257 + 256];
    float4 b4 = reinterpret_cast<const float4*>(b1)[l];
    float bs0 = 0.f, bs1 = 0.f, bs2 = 0.f, bs3 = 0.f;
    float bq0 = 0.f, bq1 = 0.f, bq2 = 0.f, bq3 = 0.f;
    int gw = (blockIdx.x * blockDim.x + tid) >> 5;
    int nw = (gridDim.x * blockDim.x) >> 5;
    for (int e = gw; e < EDGES; e += nw) {
        int r = rowp[e], c = colp[e];
        float d = (l < 3) ? (coord[r * 3 + l] - coord[c * 3 + l]) : 0.f;
        float p = d * d;
        p += __shfl_xor_sync(0xffffffffu, p, 1);
        p += __shfl_xor_sync(0xffffffffu, p, 2);
        p = __shfl_sync(0xffffffffu, p, 0);
        float4 a = reinterpret_cast<const float4*>(g_preA)[r * 32 + l];
        float4 bb = reinterpret_cast<const float4*>(g_preB)[c * 32 + l];
        float v0 = a.x + bb.x + p * wr0 + b4.x;
        float v1 = a.y + bb.y + p * wr1 + b4.y;
        float v2 = a.z + bb.z + p * wr2 + b4.z;
        float v3 = a.w + bb.w + p * wr3 + b4.w;
        reinterpret_cast<float4*>(g_bufA)[(size_t)e * 32 + l] = make_float4(v0, v1, v2, v3);
        bs0 += v0; bs1 += v1; bs2 += v2; bs3 += v3;
        bq0 += v0 * v0; bq1 += v1 * v1; bq2 += v2 * v2; bq3 += v3 * v3;
        if (l == 0) atomicAdd(&g_cnt[r], 1.0f);
    }
    sred[wi * 128 + 4 * l + 0] = bs0;
    sred[wi * 128 + 4 * l + 1] = bs1;
    sred[wi * 128 + 4 * l + 2] = bs2;
    sred[wi * 128 + 4 * l + 3] = bs3;
    sred[1024 + wi * 128 + 4 * l + 0] = bq0;
    sred[1024 + wi * 128 + 4 * l + 1] = bq1;
    sred[1024 + wi * 128 + 4 * l + 2] = bq2;
    sred[1024 + wi * 128 + 4 * l + 3] = bq3;
    __syncthreads();
    if (tid < 128) {
        float s = 0.f, q = 0.f;
#pragma unroll
        for (int gi = 0; gi < 8; gi++) {
            s += sred[gi * 128 + tid];
            q += sred[1024 + gi * 128 + tid];
        }
        atomicAdd(&g_bnsum[tid], s);
        atomicAdd(&g_bnsum[128 + tid], q);
    }
}

// Edge GEMM: 64-row tile, 128 threads, 8 rows x (4+4) cols per thread, 2 CTAs/SM.
// BN affine for the input layer computed inline from g_bnsum (no k_bn_fin kernel).
template <bool DO_AGG>
__global__ void __launch_bounds__(NT2, 2) k_edge_mid(const float* __restrict__ W,
                                                     const float* __restrict__ bvec,
                                                     const int* __restrict__ rowp,
                                                     const float* __restrict__ gvec,
                                                     const float* __restrict__ bevec) {
    extern __shared__ float sm[];
    float* Ws = sm;
    float* in_t = Ws + DD * WPAD;
    int* rowi = reinterpret_cast<int*>(in_t + TILE * IPAD2);
    const float* src = DO_AGG ? g_bufB : g_bufA;
    float* dst = DO_AGG ? g_bufA : g_bufB;
    const int li_in = DO_AGG ? 1 : 0;
    const int li_out = DO_AGG ? 2 : 1;
    int tid = threadIdx.x;
    for (int idx = tid; idx < DD * DD; idx += NT2) {
        int o = idx >> 7, k = idx & 127;
        Ws[k * WPAD + o] = W[idx];
    }
    int wi = tid >> 5, l = tid & 31;
    int tx = tid & 15, ty = tid >> 4;  // ty in 0..7
    int ob1 = tx * 4, ob2 = 64 + tx * 4;
    float4 sc4, sh4;
    bn_affine(li_in, (float)EDGES, gvec, bevec, l, sc4, sh4);
    float bias[8];
#pragma unroll
    for (int j = 0; j < 4; j++) {
        bias[j] = bvec[ob1 + j];
        bias[4 + j] = bvec[ob2 + j];
    }
    __syncthreads();
    for (int tile = blockIdx.x; tile < EDGES / TILE; tile += gridDim.x) {
        int e0 = tile * TILE;
        for (int el = wi; el < TILE; el += 4) {
            int e = e0 + el;
            float4 v = reinterpret_cast<const float4*>(src)[(size_t)e * 32 + l];
            v.x = fmaxf(fmaf(v.x, sc4.x, sh4.x), 0.f);
            v.y = fmaxf(fmaf(v.y, sc4.y, sh4.y), 0.f);
            v.z = fmaxf(fmaf(v.z, sc4.z, sh4.z), 0.f);
            v.w = fmaxf(fmaf(v.w, sc4.w, sh4.w), 0.f);
            *reinterpret_cast<float4*>(&in_t[el * IPAD2 + 4 * l]) = v;
            if (DO_AGG && l == 0) rowi[el] = rowp[e];
        }
        __syncthreads();
        if (DO_AGG) {
            for (int t2 = tid; t2 < TILE * 32; t2 += NT2) {
                int el = t2 >> 5, ch = t2 & 31;
                float4 v = *reinterpret_cast<const float4*>(&in_t[el * IPAD2 + ch * 4]);
                float* dp = &g_agg[rowi[el] * DD + ch * 4];
                asm volatile("red.global.add.v4.f32 [%0], {%1,%2,%3,%4};" ::"l"(dp), "f"(v.x),
                             "f"(v.y), "f"(v.z), "f"(v.w)
                             : "memory");
            }
        }
        u64 acc[8][4];
        gemm_core8(Ws, in_t, acc, tx, ty);
        float bs[8], bq[8];
#pragma unroll
        for (int j = 0; j < 8; j++) { bs[j] = 0.f; bq[j] = 0.f; }
#pragma unroll
        for (int i = 0; i < 8; i++) {
            int e = e0 + ty * 8 + i;
            float v[8];
            unpack_row(acc[i], v);
#pragma unroll
            for (int j = 0; j < 8; j++) {
                v[j] += bias[j];
                bs[j] += v[j];
                bq[j] += v[j] * v[j];
            }
            *reinterpret_cast<float4*>(&dst[(size_t)e * DD + ob1]) =
                make_float4(v[0], v[1], v[2], v[3]);
            *reinterpret_cast<float4*>(&dst[(size_t)e * DD + ob2]) =
                make_float4(v[4], v[5], v[6], v[7]);
        }
        tile_stats8(in_t, bs, bq, ob1, ob2, ty, tid, li_out);
    }
}

__global__ void k_coord(const float* __restrict__ coord, const int* __restrict__ rowp,
                        const int* __restrict__ colp, const float* __restrict__ cw2,
                        const float* __restrict__ gvec, const float* __restrict__ bevec) {
    int l = threadIdx.x & 31;
    int gw = (blockIdx.x * blockDim.x + threadIdx.x) >> 5;
    int nw = (gridDim.x * blockDim.x) >> 5;
    float4 sc, sh;
    bn_affine(2, (float)EDGES, gvec, bevec, l, sc, sh);
    float4 w4 = reinterpret_cast<const float4*>(cw2)[l];
    for (int e = gw; e < EDGES; e += nw) {
        float4 y = reinterpret_cast<const float4*>(g_bufA)[(size_t)e * 32 + l];
        y.x = fmaxf(fmaf(y.x, sc.x, sh.x), 0.f);
        y.y = fmaxf(fmaf(y.y, sc.y, sh.y), 0.f);
        y.z = fmaxf(fmaf(y.z, sc.z, sh.z), 0.f);
        y.w = fmaxf(fmaf(y.w, sc.w, sh.w), 0.f);
        float p = y.x * w4.x + y.y * w4.y + y.z * w4.z + y.w * w4.w;
#pragma unroll
        for (int off = 16; off > 0; off >>= 1) p += __shfl_xor_sync(0xffffffffu, p, off);
        if (l < 3) {
            int r = rowp[e], c = colp[e];
            float d = coord[r * 3 + l] - coord[c * 3 + l];
            float t = fminf(fmaxf(d * p, -100.f), 100.f);
            atomicAdd(&g_csum[r * 3 + l], t);
        }
    }
}

__global__ void __launch_bounds__(NT) k_node1(const float* __restrict__ h,
                                              const float* __restrict__ W,
                                              const float* __restrict__ bvec) {
    extern __shared__ float sm[];
    float* Ws = sm;
    float* in_t = Ws + 256 * WPAD;
    int tid = threadIdx.x;
    for (int idx = tid; idx < DD * 256; idx += NT) {
        int o = idx >> 8, k = idx & 255;
        Ws[k * WPAD + o] = W[idx];
    }
    int wi = tid >> 5, l = tid & 31;
    int tx = tid & 15, ty = tid >> 4;
    int ob1 = tx * 4, ob2 = 64 + tx * 4;
    float bias[8];
#pragma unroll
    for (int j = 0; j < 4; j++) {
        bias[j] = bvec[ob1 + j];
        bias[4 + j] = bvec[ob2 + j];
    }
    __syncthreads();
    int ntiles = (NODES + TILE - 1) / TILE;
    for (int tile = blockIdx.x; tile < ntiles; tile += gridDim.x) {
        int n0 = tile * TILE;
        for (int el = wi; el < TILE; el += 8) {
            int n = n0 + el;
            if (n < NODES) {
                float4 hv = reinterpret_cast<const float4*>(h)[n * 32 + l];
                *reinterpret_cast<float4*>(&in_t[el * IPADN + 4 * l]) = hv;
                float invc = 1.f / fmaxf(g_cnt[n], 1.f);
                float4 av = reinterpret_cast<const float4*>(g_agg)[n * 32 + l];
                av.x *= invc; av.y *= invc; av.z *= invc; av.w *= invc;
                *reinterpret_cast<float4*>(&in_t[el * IPADN + DD + 4 * l]) = av;
            } else {
                float4 z = make_float4(0.f, 0.f, 0.f, 0.f);
                *reinterpret_cast<float4*>(&in_t[el * IPADN + 4 * l]) = z;
                *reinterpret_cast<float4*>(&in_t[el * IPADN + DD + 4 * l]) = z;
            }
        }
        __syncthreads();
        u64 acc[4][4];
        gemm_core<256, IPADN>(Ws, in_t, acc, tx, ty);
        float bs[8], bq[8];
#pragma unroll
        for (int j = 0; j < 8; j++) { bs[j] = 0.f; bq[j] = 0.f; }
#pragma unroll
        for (int i = 0; i < 4; i++) {
            int n = n0 + ty * 4 + i;
            float v[8];
            unpack_row(acc[i], v);
#pragma unroll
            for (int j = 0; j < 8; j++) v[j] += bias[j];
            if (n < NODES) {
#pragma unroll
                for (int j = 0; j < 8; j++) {
                    bs[j] += v[j];
                    bq[j] += v[j] * v[j];
                }
                *reinterpret_cast<float4*>(&g_npre[n * DD + ob1]) =
                    make_float4(v[0], v[1], v[2], v[3]);
                *reinterpret_cast<float4*>(&g_npre[n * DD + ob2]) =
                    make_float4(v[4], v[5], v[6], v[7]);
            }
        }
        tile_stats(in_t, bs, bq, ob1, ob2, ty, tid, 3);
    }
}

__global__ void __launch_bounds__(NT, 2) k_node2(const float* __restrict__ h,
                                                 const float* __restrict__ W,
                                                 const float* __restrict__ bvec,
                                                 float* __restrict__ out,
                                                 const float* __restrict__ gvec,
                                                 const float* __restrict__ bevec) {
    extern __shared__ float sm[];
    float* Ws = sm;
    float* in_t = Ws + DD * WPAD;
    int tid = threadIdx.x;
    for (int idx = tid; idx < DD * DD; idx += NT) {
        int o = idx >> 7, k = idx & 127;
        Ws[k * WPAD + o] = W[idx];
    }
    int wi = tid >> 5, l = tid & 31;
    int tx = tid & 15, ty = tid >> 4;
    int ob1 = tx * 4, ob2 = 64 + tx * 4;
    float4 sc4, sh4;
    bn_affine(3, (float)NODES, gvec, bevec, l, sc4, sh4);
    float bias[8];
#pragma unroll
    for (int j = 0; j < 4; j++) {
        bias[j] = bvec[ob1 + j];
        bias[4 + j] = bvec[ob2 + j];
    }
    __syncthreads();
    int ntiles = (NODES + TILE - 1) / TILE;
    for (int tile = blockIdx.x; tile < ntiles; tile += gridDim.x) {
        int n0 = tile * TILE;
        for (int el = wi; el < TILE; el += 8) {
            int n = n0 + el;
            float4 v = make_float4(0.f, 0.f, 0.f, 0.f);
            if (n < NODES) {
                v = reinterpret_cast<const float4*>(g_npre)[n * 32 + l];
                v.x = fmaxf(fmaf(v.x, sc4.x, sh4.x), 0.f);
                v.y = fmaxf(fmaf(v.y, sc4.y, sh4.y), 0.f);
                v.z = fmaxf(fmaf(v.z, sc4.z, sh4.z), 0.f);
                v.w = fmaxf(fmaf(v.w, sc4.w, sh4.w), 0.f);
            }
            *reinterpret_cast<float4*>(&in_t[el * IPAD2 + 4 * l]) = v;
        }
        __syncthreads();
        u64 acc[4][4];
        gemm_core<DD, IPAD2>(Ws, in_t, acc, tx, ty);
#pragma unroll
        for (int i = 0; i < 4; i++) {
            int n = n0 + ty * 4 + i;
            if (n < NODES) {
                float v[8];
                unpack_row(acc[i], v);
#pragma unroll
                for (int j = 0; j < 4; j++) {
                    v[j] += bias[j] + h[n * DD + ob1 + j];
                    v[4 + j] += bias[4 + j] + h[n * DD + ob2 + j];
                }
                *reinterpret_cast<float4*>(&out[n * DD + ob1]) =
                    make_float4(v[0], v[1], v[2], v[3]);
                *reinterpret_cast<float4*>(&out[n * DD + ob2]) =
                    make_float4(v[4], v[5], v[6], v[7]);
            }
        }
        __syncthreads();
    }
}

__global__ void k_coord_fin(const float* __restrict__ coord, float* __restrict__ out) {
    int i = blockIdx.x * blockDim.x + threadIdx.x;
    if (i < NODES * 3)
        out[NODES * DD + i] = coord[i] + g_csum[i] / fmaxf(g_cnt[i / 3], 1.f);
}

extern "C" void kernel_launch(void* const* d_in, const int* in_sizes, int n_in,
                              void* d_out, int out_size) {
    const float* h = (const float*)d_in[0];
    const float* coord = (const float*)d_in[1];
    const int* ei = (const int*)d_in[2];
    const float* e_w1 = (const float*)d_in[3];
    const float* e_b1 = (const float*)d_in[4];
    const float* e_g1 = (const float*)d_in[5];
    const float* e_be1 = (const float*)d_in[6];
    const float* e_w2 = (const float*)d_in[7];
    const float* e_b2 = (const float*)d_in[8];
    const float* e_g2 = (const float*)d_in[9];
    const float* e_be2 = (const float*)d_in[10];
    const float* n_w1 = (const float*)d_in[11];
    const float* n_b1 = (const float*)d_in[12];
    const float* n_g1 = (const float*)d_in[13];
    const float* n_be1 = (const float*)d_in[14];
    const float* n_w2 = (const float*)d_in[15];
    const float* n_b2 = (const float*)d_in[16];
    const float* c_w1 = (const float*)d_in[17];
    const float* c_b1 = (const float*)d_in[18];
    const float* c_g1 = (const float*)d_in[19];
    const float* c_be1 = (const float*)d_in[20];
    const float* c_w2 = (const float*)d_in[21];
    const int* rowp = ei;
    const int* colp = ei + EDGES;
    float* out = (float*)d_out;

    int S2 = (DD * WPAD + TILE * IPAD2) * 4 + TILE * 4;
    int Sn1 = (256 * WPAD + TILE * IPADN) * 4;
    cudaFuncSetAttribute(k_pre<0>, cudaFuncAttributeMaxDynamicSharedMemorySize, S2);
    cudaFuncSetAttribute(k_pre<1>, cudaFuncAttributeMaxDynamicSharedMemorySize, S2);
    cudaFuncSetAttribute(k_edge_mid<false>, cudaFuncAttributeMaxDynamicSharedMemorySize, S2);
    cudaFuncSetAttribute(k_edge_mid<true>, cudaFuncAttributeMaxDynamicSharedMemorySize, S2);
    cudaFuncSetAttribute(k_node1, cudaFuncAttributeMaxDynamicSharedMemorySize, Sn1);
    cudaFuncSetAttribute(k_node2, cudaFuncAttributeMaxDynamicSharedMemorySize, S2);

    k_zero<<<592, 256>>>();
    k_pre<0><<<296, NT, S2>>>(h, e_w1, 257, 0);
    k_pre<1><<<296, NT, S2>>>(h, e_w1, 257, 128);
    k_e1gather<<<740, 256>>>(coord, rowp, colp, e_w1, e_b1);
    k_edge_mid<false><<<296, NT2, S2>>>(e_w2, e_b2, rowp, e_g1, e_be1);
    k_edge_mid<true><<<296, NT2, S2>>>(c_w1, c_b1, rowp, e_g2, e_be2);
    k_coord<<<740, 256>>>(coord, rowp, colp, c_w2, c_g1, c_be1);
    k_node1<<<148, NT, Sn1>>>(h, n_w1, n_b1);
    k_node2<<<296, NT, S2>>>(h, n_w2, n_b2, out, n_g1, n_be1);
    k_coord_fin<<<(NODES * 3 + 255) / 256, 256>>>(coord, out);
}